// round 8
// baseline (speedup 1.0000x reference)
#include <cuda_runtime.h>
#include <math.h>

// Problem constants
#define KDIM 128
#define BDIM 16
#define LDIM 8192
#define NF   256            // fine grid (oversampling sigma = 2)
#define WHALF 2.5f          // window half-width (w = 5)
#define BETA  11.5f         // ES beta = 2.30 * w
#define PI_F 3.14159265358979f

#define FSTRIDE 272         // fine-grid row stride (256 + 8 halo + 8 pad)
#define FBATCH  (NF * FSTRIDE)
#define LUTN 1600           // window LUT entries, step 1/512

// Scratch (device globals; no cudaMalloc allowed)
__device__ float  d_phi[65];
__device__ float  d_ctab[256];
__device__ float  d_cos256[256];
__device__ float  d_corner[BDIM];
__device__ float2 d_wlut[LUTN];
__device__ float  d_g[BDIM * KDIM * NF];
__device__ float  d_f[BDIM * FBATCH];

__device__ __forceinline__ float es_win(float dist) {
    float z = dist * (1.0f / WHALF);
    float t = 1.0f - z * z;
    if (t <= 0.0f) return 0.0f;
    return expf(BETA * (sqrtf(t) - 1.0f));
}

// ---------------------------------------------------------------------------
// Prep kernel, grid 89 x 256:
//  blocks 0..64  : Phi_k quadrature    blocks 65..71 : window LUT
//  blocks 72..87 : per-batch corner    block 88      : cos table
// ---------------------------------------------------------------------------
__global__ void prep_kernel(const float* __restrict__ psi) {
    int bid = blockIdx.x;
    int tid = threadIdx.x;

    if (bid < 65) {
        __shared__ float red[256];
        const int NQ = 512;
        float h = (2.0f * WHALF) / NQ;
        float k = (float)bid;
        float acc = 0.0f;
        #pragma unroll
        for (int r = 0; r < 2; r++) {
            int i = tid + r * 256;
            float t = -WHALF + (i + 0.5f) * h;
            acc += es_win(fabsf(t)) * cospif(k * t * (1.0f / 128.0f));
        }
        red[tid] = acc;
        __syncthreads();
        for (int s = 128; s > 0; s >>= 1) {
            if (tid < s) red[tid] += red[tid + s];
            __syncthreads();
        }
        if (tid == 0) d_phi[bid] = red[0] * h;
    } else if (bid < 72) {
        int i = (bid - 65) * 256 + tid;
        if (i < LUTN) {
            float h = 1.0f / 512.0f;
            float v0 = es_win((float)i * h);
            float v1 = es_win((float)(i + 1) * h);
            d_wlut[i] = make_float2(v0, v1 - v0);
        }
    } else if (bid < 88) {
        __shared__ float red[256];
        int b = bid - 72;
        const float* p = psi + b * (KDIM * KDIM);
        float acc = 0.0f;
        for (int idx = tid; idx < KDIM * KDIM; idx += 256) {
            float v = p[idx];
            int par = ((idx >> 7) ^ idx) & 1;
            acc += par ? -v : v;
        }
        red[tid] = acc;
        __syncthreads();
        for (int s = 128; s > 0; s >>= 1) {
            if (tid < s) red[tid] += red[tid + s];
            __syncthreads();
        }
        if (tid == 0) d_corner[b] = red[0];
    } else {
        d_cos256[tid] = cospif((float)tid * (1.0f / 128.0f));
    }
}

// ---------------------------------------------------------------------------
// c-table combine: trig via cos table.
// ---------------------------------------------------------------------------
__global__ void ctab_kernel() {
    __shared__ float sD[65];
    __shared__ float sc[256];
    int tid = threadIdx.x;
    sc[tid] = d_cos256[tid];
    if (tid < 65) sD[tid] = 1.0f / d_phi[tid];
    __syncthreads();
    int d = tid;
    float s = sD[0];
    #pragma unroll 8
    for (int k = 1; k < 64; k++) {
        s = fmaf(2.0f * sD[k], sc[(k * d) & 255], s);
    }
    s = fmaf(sD[64], sc[(64 * d) & 255], s);
    d_ctab[d] = s * (1.0f / 128.0f);
}

// ---------------------------------------------------------------------------
// Stage 1: g[b,m,v] = sum_n psi[b,m,n] * c[(v - 2n) mod 256]
// tile 32(m) x 64(v), 128 threads, micro 4x4.
// A (psi) staged TRANSPOSED in smem (As[n][m]) so the a-frag is one LDS.128;
// B (ctab) read directly from a duplicated 512-entry table.
// Inner loop explicitly double-buffered (prefetch k+1 before FMAs of k).
// grid: (4 v, 4 m, 16 b)
// ---------------------------------------------------------------------------
__global__ void __launch_bounds__(128) stage1_kernel(const float* __restrict__ psi) {
    __shared__ float cs2[512];
    __shared__ __align__(16) float As[32][36];   // [n-local][m-local]
    int b  = blockIdx.z;
    int m0 = blockIdx.y * 32;
    int v0 = blockIdx.x * 64;
    int tid = threadIdx.x;
    #pragma unroll
    for (int i = 0; i < 4; i++)
        cs2[tid + i * 128] = d_ctab[(tid + i * 128) & 255];
    int tx = tid & 15, ty = tid >> 4;       // tx: v/4 (0..15), ty: m/4 (0..7)
    float acc[4][4] = {};
    const float* P = psi + b * (KDIM * KDIM);

    for (int n0 = 0; n0 < KDIM; n0 += 32) {
        __syncthreads();
        #pragma unroll
        for (int i = 0; i < 2; i++) {
            int u = tid + i * 128;           // 256 float4 units: 32 m x 8 n4
            int ml = u >> 3, n4 = (u & 7) * 4;
            float4 a = *(const float4*)&P[(m0 + ml) * KDIM + n0 + n4];
            As[n4 + 0][ml] = a.x;
            As[n4 + 1][ml] = a.y;
            As[n4 + 2][ml] = a.z;
            As[n4 + 3][ml] = a.w;
        }
        __syncthreads();
        int bbase = v0 + tx * 4 + 256 - 2 * n0;
        float4 av[2]; float2 b0[2], b1[2];
        av[0] = *(const float4*)&As[0][ty * 4];
        b0[0] = *(const float2*)&cs2[bbase];
        b1[0] = *(const float2*)&cs2[bbase + 2];
        #pragma unroll
        for (int nk = 0; nk < 32; nk++) {
            int cur = nk & 1, nxt = cur ^ 1;
            if (nk < 31) {
                int bi = bbase - 2 * (nk + 1);
                av[nxt] = *(const float4*)&As[nk + 1][ty * 4];
                b0[nxt] = *(const float2*)&cs2[bi];
                b1[nxt] = *(const float2*)&cs2[bi + 2];
            }
            float4 a = av[cur];
            float2 p0 = b0[cur], p1 = b1[cur];
            acc[0][0] = fmaf(a.x, p0.x, acc[0][0]);
            acc[0][1] = fmaf(a.x, p0.y, acc[0][1]);
            acc[0][2] = fmaf(a.x, p1.x, acc[0][2]);
            acc[0][3] = fmaf(a.x, p1.y, acc[0][3]);
            acc[1][0] = fmaf(a.y, p0.x, acc[1][0]);
            acc[1][1] = fmaf(a.y, p0.y, acc[1][1]);
            acc[1][2] = fmaf(a.y, p1.x, acc[1][2]);
            acc[1][3] = fmaf(a.y, p1.y, acc[1][3]);
            acc[2][0] = fmaf(a.z, p0.x, acc[2][0]);
            acc[2][1] = fmaf(a.z, p0.y, acc[2][1]);
            acc[2][2] = fmaf(a.z, p1.x, acc[2][2]);
            acc[2][3] = fmaf(a.z, p1.y, acc[2][3]);
            acc[3][0] = fmaf(a.w, p0.x, acc[3][0]);
            acc[3][1] = fmaf(a.w, p0.y, acc[3][1]);
            acc[3][2] = fmaf(a.w, p1.x, acc[3][2]);
            acc[3][3] = fmaf(a.w, p1.y, acc[3][3]);
        }
    }
    float* G = d_g + b * (KDIM * NF);
    #pragma unroll
    for (int i = 0; i < 4; i++) {
        float4 o = make_float4(acc[i][0], acc[i][1], acc[i][2], acc[i][3]);
        *(float4*)&G[(m0 + ty * 4 + i) * NF + v0 + tx * 4] = o;
    }
}

// ---------------------------------------------------------------------------
// Stage 2: f[b,u,v] = sum_m c[(u - 2m) mod 256] * g[b,m,v]
// tile 32(u) x 64(v), 128 threads, micro 4x4.
// B (g) staged in smem; A (ctab) from duplicated table via broadcast LDS.64.
// Inner loop explicitly double-buffered (prefetch k+1 before FMAs of k).
// grid: (4 v, 8 u, 16 b). Writes padded layout (+4 x offset) and x halo.
// ---------------------------------------------------------------------------
__global__ void __launch_bounds__(128) stage2_kernel() {
    __shared__ float cs2[512];
    __shared__ __align__(16) float Bs[32][68];   // [m-local][v-local]
    int b  = blockIdx.z;
    int u0 = blockIdx.y * 32;
    int v0 = blockIdx.x * 64;
    int tid = threadIdx.x;
    #pragma unroll
    for (int i = 0; i < 4; i++)
        cs2[tid + i * 128] = d_ctab[(tid + i * 128) & 255];
    int tx = tid & 15, ty = tid >> 4;       // tx: v/4, ty: u/4
    float acc[4][4] = {};
    const float* G = d_g + b * (KDIM * NF);

    for (int m0 = 0; m0 < KDIM; m0 += 32) {
        __syncthreads();
        #pragma unroll
        for (int i = 0; i < 4; i++) {
            int u = tid + i * 128;           // float4 units: 32 m x 16 v4
            int mk = u >> 4, v4 = (u & 15) * 4;
            *(float4*)&Bs[mk][v4] = *(const float4*)&G[(m0 + mk) * NF + v0 + v4];
        }
        __syncthreads();
        int abase = u0 + ty * 4 + 256 - 2 * m0;
        float4 bv[2]; float2 a0[2], a1[2];
        bv[0] = *(const float4*)&Bs[0][tx * 4];
        a0[0] = *(const float2*)&cs2[abase];
        a1[0] = *(const float2*)&cs2[abase + 2];
        #pragma unroll
        for (int mk = 0; mk < 32; mk++) {
            int cur = mk & 1, nxt = cur ^ 1;
            if (mk < 31) {
                int ai = abase - 2 * (mk + 1);
                bv[nxt] = *(const float4*)&Bs[mk + 1][tx * 4];
                a0[nxt] = *(const float2*)&cs2[ai];
                a1[nxt] = *(const float2*)&cs2[ai + 2];
            }
            float4 bb = bv[cur];
            float2 q0 = a0[cur], q1 = a1[cur];
            acc[0][0] = fmaf(q0.x, bb.x, acc[0][0]);
            acc[0][1] = fmaf(q0.x, bb.y, acc[0][1]);
            acc[0][2] = fmaf(q0.x, bb.z, acc[0][2]);
            acc[0][3] = fmaf(q0.x, bb.w, acc[0][3]);
            acc[1][0] = fmaf(q0.y, bb.x, acc[1][0]);
            acc[1][1] = fmaf(q0.y, bb.y, acc[1][1]);
            acc[1][2] = fmaf(q0.y, bb.z, acc[1][2]);
            acc[1][3] = fmaf(q0.y, bb.w, acc[1][3]);
            acc[2][0] = fmaf(q1.x, bb.x, acc[2][0]);
            acc[2][1] = fmaf(q1.x, bb.y, acc[2][1]);
            acc[2][2] = fmaf(q1.x, bb.z, acc[2][2]);
            acc[2][3] = fmaf(q1.x, bb.w, acc[2][3]);
            acc[3][0] = fmaf(q1.y, bb.x, acc[3][0]);
            acc[3][1] = fmaf(q1.y, bb.y, acc[3][1]);
            acc[3][2] = fmaf(q1.y, bb.z, acc[3][2]);
            acc[3][3] = fmaf(q1.y, bb.w, acc[3][3]);
        }
    }

    float* F = d_f + b * FBATCH;
    int col = v0 + tx * 4;
    #pragma unroll
    for (int i = 0; i < 4; i++) {
        int row = u0 + ty * 4 + i;
        float4 o = make_float4(acc[i][0], acc[i][1], acc[i][2], acc[i][3]);
        *(float4*)&F[row * FSTRIDE + col + 4] = o;
        if (col == 0)   *(float4*)&F[row * FSTRIDE + 260] = o;  // right halo
        if (col == 252) *(float4*)&F[row * FSTRIDE + 0]   = o;  // left halo
    }
}

// ---------------------------------------------------------------------------
// Interpolation: one thread per point, w=5 ES window via shared LUT.
// ---------------------------------------------------------------------------
__global__ void interp_kernel(const float* __restrict__ x0,
                              const float* __restrict__ y0,
                              float* __restrict__ out) {
    __shared__ float2 slut[LUTN];
    int tid = threadIdx.x;
    for (int i = tid; i < LUTN; i += 256) slut[i] = d_wlut[i];
    __syncthreads();

    int p = blockIdx.x * 256 + tid;
    int b = p >> 13;
    float x = x0[p], y = y0[p];
    float txr = x * (128.0f / PI_F);
    float tyr = y * (128.0f / PI_F);
    float tx = txr + 256.0f;
    float ty = tyr + 256.0f;
    if (tx >= 256.0f) tx -= 256.0f;
    if (ty >= 256.0f) ty -= 256.0f;

    float fx = floorf(tx), fy = floorf(ty);
    int ix0 = (int)fx, iy0 = (int)fy;
    float dx = tx - fx, dy = ty - fy;

    int ic0 = ix0 - 2 + (dx >= 0.5f);
    int xb  = ic0 & ~3;
    int ir0 = iy0 - 2 + (dy >= 0.5f);

    float wx[8];
    #pragma unroll
    for (int j = 0; j < 8; j++) {
        float d  = fabsf(tx - (float)(xb + j));
        float fi = d * 512.0f;
        int idx  = (int)fi;
        float fr = fi - (float)idx;
        if (idx > LUTN - 1) { idx = LUTN - 1; fr = 0.0f; }
        float2 e = slut[idx];
        wx[j] = fmaf(fr, e.y, e.x);
    }
    float wy[5];
    #pragma unroll
    for (int a = 0; a < 5; a++) {
        float d  = fabsf(ty - (float)(ir0 + a));
        float fi = d * 512.0f;
        int idx  = (int)fi;
        float fr = fi - (float)idx;
        if (idx > LUTN - 1) { idx = LUTN - 1; fr = 0.0f; }
        float2 e = slut[idx];
        wy[a] = fmaf(fr, e.y, e.x);
    }

    const float* Fb = d_f + b * FBATCH;
    float acc = 0.0f;
    #pragma unroll
    for (int a = 0; a < 5; a++) {
        int row = (ir0 + a) & 255;
        const float4* rp = (const float4*)(Fb + row * FSTRIDE + xb + 4);
        float4 A = __ldg(rp);
        float4 Bv = __ldg(rp + 1);
        float rs = wx[0] * A.x + wx[1] * A.y + wx[2] * A.z + wx[3] * A.w
                 + wx[4] * Bv.x + wx[5] * Bv.y + wx[6] * Bv.z + wx[7] * Bv.w;
        acc = fmaf(wy[a], rs, acc);
    }

    float corr = d_corner[b] * (1.0f / 16384.0f) *
                 sinpif(0.5f * txr) * sinpif(0.5f * tyr);
    out[p] = acc - corr;
}

// ---------------------------------------------------------------------------
extern "C" void kernel_launch(void* const* d_in, const int* in_sizes, int n_in,
                              void* d_out, int out_size) {
    const float* x0  = (const float*)d_in[0];
    const float* y0  = (const float*)d_in[1];
    const float* psi = (const float*)d_in[2];
    float* out = (float*)d_out;

    prep_kernel<<<89, 256>>>(psi);
    ctab_kernel<<<1, 256>>>();
    stage1_kernel<<<dim3(4, 4, BDIM), 128>>>(psi);
    stage2_kernel<<<dim3(4, 8, BDIM), 128>>>();
    interp_kernel<<<512, 256>>>(x0, y0, out);
}